// round 10
// baseline (speedup 1.0000x reference)
#include <cuda_runtime.h>

#define NN    100000
#define EMAX  1700000
#define INC   128
#define H1DIM 64
#define HEADS 8
#define HID   8
#define OUTC  40
#define FULL  0xffffffffu
#define SCANB 98            // ceil(NN/1024)

// ---- scratch ----
__device__ float  g_h1[NN * H1DIM];
__device__ float4 g_pas1[NN * HEADS];   // (a_s, e^{a_s}, e^{0.2 a_s}, 0) per node-head
__device__ float  g_ad1[NN * HEADS];
__device__ float  g_act1[NN * H1DIM];
__device__ float  g_h2[NN * OUTC];
__device__ float4 g_pas2[NN];           // (a_s, e^{a_s}, e^{0.2 a_s}, 0) per node
__device__ float  g_ad2[NN];
__device__ int    g_cnt[NN];
__device__ int    g_cur[NN];
__device__ int    g_rowptr[NN + 1];
__device__ int    g_blocksum[SCANB];
__device__ int    g_csr_src[EMAX];

// ---- zero the CSR counters ----
__global__ void __launch_bounds__(256) k_init() {
    int i = blockIdx.x * blockDim.x + threadIdx.x;
    if (i < NN) { g_cnt[i] = 0; g_cur[i] = 0; }
}

// ---- histogram of destinations ----
__global__ void __launch_bounds__(256) k_hist(const int* __restrict__ dst, int nE) {
    int e = blockIdx.x * blockDim.x + threadIdx.x;
    if (e < nE) atomicAdd(&g_cnt[dst[e]], 1);
}

// ---- scan phase A ----
__global__ void __launch_bounds__(1024) k_scanA() {
    __shared__ int sm[1024];
    int t = threadIdx.x;
    int i = blockIdx.x * 1024 + t;
    sm[t] = (i < NN) ? g_cnt[i] : 0;
    __syncthreads();
    for (int d = 512; d > 0; d >>= 1) {
        if (t < d) sm[t] += sm[t + d];
        __syncthreads();
    }
    if (t == 0) g_blocksum[blockIdx.x] = sm[0];
}

// ---- scan phase B ----
__global__ void __launch_bounds__(128) k_scanB() {
    __shared__ int sm[128];
    int t = threadIdx.x;
    int v = (t < SCANB) ? g_blocksum[t] : 0;
    sm[t] = v;
    __syncthreads();
    for (int d = 1; d < 128; d <<= 1) {
        int u = (t >= d) ? sm[t - d] : 0;
        __syncthreads();
        sm[t] += u;
        __syncthreads();
    }
    if (t < SCANB) g_blocksum[t] = sm[t] - v;   // exclusive offsets (in place)
    if (t == SCANB - 1) g_rowptr[NN] = sm[t];
}

// ---- scan phase C ----
__global__ void __launch_bounds__(1024) k_scanC() {
    __shared__ int sm[1024];
    int t = threadIdx.x;
    int i = blockIdx.x * 1024 + t;
    int v = (i < NN) ? g_cnt[i] : 0;
    sm[t] = v;
    __syncthreads();
    for (int d = 1; d < 1024; d <<= 1) {
        int u = (t >= d) ? sm[t - d] : 0;
        __syncthreads();
        sm[t] += u;
        __syncthreads();
    }
    if (i < NN) g_rowptr[i] = g_blocksum[blockIdx.x] + sm[t] - v;
}

// ---- CSR fill ----
__global__ void __launch_bounds__(256) k_fill(const int* __restrict__ src,
                                              const int* __restrict__ dst, int nE) {
    int e = blockIdx.x * blockDim.x + threadIdx.x;
    if (e >= nE) return;
    int d = dst[e];
    int p = g_rowptr[d] + atomicAdd(&g_cur[d], 1);
    g_csr_src[p] = src[e];
}

// ---- layer-1 GEMM + attention dots + exp factor tables ----
__global__ void __launch_bounds__(256) k_gemm1(
        const float* __restrict__ x,  const float* __restrict__ W1,
        const float* __restrict__ as_w, const float* __restrict__ ad_w) {
    __shared__ float wT[INC * H1DIM];
    __shared__ float xs[16 * INC];
    const int t = threadIdx.x;
    const int nb = blockIdx.x * 16;

    for (int i = t; i < H1DIM * INC; i += 256) {
        int f = i >> 7, k = i & 127;
        wT[k * H1DIM + f] = W1[i];
    }
    for (int i = t; i < 16 * INC; i += 256) {
        int node = nb + (i >> 7);
        xs[i] = x[node * INC + (i & 127)];
    }
    __syncthreads();

    const int f = t & 63;
    const int g = t >> 6;
    float acc[4] = {0.f, 0.f, 0.f, 0.f};

    const float4* xr0 = (const float4*)(xs + (g +  0) * INC);
    const float4* xr1 = (const float4*)(xs + (g +  4) * INC);
    const float4* xr2 = (const float4*)(xs + (g +  8) * INC);
    const float4* xr3 = (const float4*)(xs + (g + 12) * INC);

    #pragma unroll 4
    for (int k4 = 0; k4 < INC / 4; k4++) {
        int kb = k4 * 4;
        float w0 = wT[(kb + 0) * H1DIM + f];
        float w1 = wT[(kb + 1) * H1DIM + f];
        float w2 = wT[(kb + 2) * H1DIM + f];
        float w3 = wT[(kb + 3) * H1DIM + f];
        float4 v;
        v = xr0[k4]; acc[0] += v.x*w0 + v.y*w1 + v.z*w2 + v.w*w3;
        v = xr1[k4]; acc[1] += v.x*w0 + v.y*w1 + v.z*w2 + v.w*w3;
        v = xr2[k4]; acc[2] += v.x*w0 + v.y*w1 + v.z*w2 + v.w*w3;
        v = xr3[k4]; acc[3] += v.x*w0 + v.y*w1 + v.z*w2 + v.w*w3;
    }

    float aw = as_w[f], dw = ad_w[f];
    #pragma unroll
    for (int i = 0; i < 4; i++) {
        int node = nb + g + 4 * i;
        float vs = acc[i] * aw, vd = acc[i] * dw;
        #pragma unroll
        for (int off = 1; off < HID; off <<= 1) {
            vs += __shfl_xor_sync(FULL, vs, off);
            vd += __shfl_xor_sync(FULL, vd, off);
        }
        g_h1[node * H1DIM + f] = acc[i];
        if ((f & 7) == 0) {
            int h = f >> 3;
            g_pas1[node * HEADS + h] =
                make_float4(vs, __expf(vs), __expf(0.2f * vs), 0.f);
            g_ad1[node * HEADS + h] = vd;
        }
    }
}

// ---- layer-1 aggregation: warp/node, float2 lanes, NO MUFU in loop ----
// lane l owns channels (2l, 2l+1), head hl = l>>2.
__global__ void __launch_bounds__(256, 5) k_agg1(const float* __restrict__ b1) {
    const int n = blockIdx.x * 8 + (threadIdx.x >> 5);
    const int l = threadIdx.x & 31;
    const int start = g_rowptr[n], end = g_rowptr[n + 1];

    const int g  = l >> 3;    // edge slot for exp phase
    const int h  = l & 7;     // head for exp phase
    const int hl = l >> 2;    // head of this lane's channel pair
    const float adh = __ldg(&g_ad1[n * HEADS + h]);
    const float E1d = __expf(adh);          // once per node-head
    const float E5d = __expf(0.2f * adh);
    const float2* __restrict__ H = (const float2*)g_h1;

    // prefetch chunk 0
    int m = end - start; if (m > 4) m = 4;
    int s = 0; float4 P = make_float4(0.f, 0.f, 0.f, 0.f);
    if (g < m) {
        s = __ldg(&g_csr_src[start + g]);
        P = __ldg(&g_pas1[s * HEADS + h]);
    }

    float accx = 0.f, accy = 0.f, den = 0.f;
    for (int eb = start; eb < end; eb += 4) {
        // prefetch next chunk
        int ebn = eb + 4;
        int mn = end - ebn; if (mn > 4) mn = 4;
        int sn = 0; float4 Pn = make_float4(0.f, 0.f, 0.f, 0.f);
        if (g < mn) {
            sn = __ldg(&g_csr_src[ebn + g]);
            Pn = __ldg(&g_pas1[sn * HEADS + h]);
        }

        // exp via factorization: no MUFU
        float v  = P.x + adh;
        float ex = (g < m) ? ((v > 0.f) ? P.y * E1d : P.z * E5d) : 0.f;
        den += ex;

        int s0 = __shfl_sync(FULL, s, 0);
        int s1 = __shfl_sync(FULL, s, 8);
        int s2 = __shfl_sync(FULL, s, 16);
        int s3 = __shfl_sync(FULL, s, 24);
        float x0 = __shfl_sync(FULL, ex, hl);
        float x1 = __shfl_sync(FULL, ex, 8 + hl);
        float x2 = __shfl_sync(FULL, ex, 16 + hl);
        float x3 = __shfl_sync(FULL, ex, 24 + hl);

        float2 r0 = __ldg(&H[s0 * 32 + l]);
        float2 r1 = __ldg(&H[s1 * 32 + l]);
        float2 r2 = __ldg(&H[s2 * 32 + l]);
        float2 r3 = __ldg(&H[s3 * 32 + l]);

        accx += x0*r0.x + x1*r1.x + x2*r2.x + x3*r3.x;
        accy += x0*r0.y + x1*r1.y + x2*r2.y + x3*r3.y;

        m = mn; s = sn; P = Pn;
    }
    den += __shfl_xor_sync(FULL, den, 8);
    den += __shfl_xor_sync(FULL, den, 16);       // lane l: denom of head l&7
    float dd = __shfl_sync(FULL, den, hl);

    float2 bb = __ldg(&((const float2*)b1)[l]);
    float o0 = accx / dd + bb.x;
    float o1 = accy / dd + bb.y;
    float2 r;
    r.x = (o0 > 0.f) ? o0 : expm1f(o0);
    r.y = (o1 > 0.f) ? o1 : expm1f(o1);
    ((float2*)g_act1)[n * 32 + l] = r;
}

// ---- layer-2 GEMM + fused attention dots + exp factor tables ----
__global__ void __launch_bounds__(320) k_gemm2(const float* __restrict__ W2,
                                               const float* __restrict__ as_w,
                                               const float* __restrict__ ad_w) {
    __shared__ float wT[H1DIM * OUTC];
    __shared__ float a[8 * H1DIM];
    __shared__ float ps[8 * OUTC];
    __shared__ float pd[8 * OUTC];
    const int t = threadIdx.x;
    const int nb = blockIdx.x * 8;

    for (int i = t; i < OUTC * H1DIM; i += 320) {
        int f = i >> 6, k = i & 63;
        wT[k * OUTC + f] = W2[i];
    }
    for (int i = t; i < 8 * H1DIM; i += 320) {
        int node = nb + (i >> 6);
        a[i] = g_act1[node * H1DIM + (i & 63)];
    }
    __syncthreads();

    const int f = t % OUTC;
    const int local = t / OUTC;
    const float4* ar = (const float4*)(a + local * H1DIM);
    float acc = 0.f;
    #pragma unroll 4
    for (int k4 = 0; k4 < H1DIM / 4; k4++) {
        int kb = k4 * 4;
        float4 v = ar[k4];
        acc += v.x * wT[(kb + 0) * OUTC + f];
        acc += v.y * wT[(kb + 1) * OUTC + f];
        acc += v.z * wT[(kb + 2) * OUTC + f];
        acc += v.w * wT[(kb + 3) * OUTC + f];
    }
    g_h2[(nb + local) * OUTC + f] = acc;
    ps[local * OUTC + f] = acc * as_w[f];
    pd[local * OUTC + f] = acc * ad_w[f];
    __syncthreads();

    if (t < 16) {
        int node = t & 7;
        const float* p = (t < 8) ? (ps + node * OUTC) : (pd + node * OUTC);
        float s = 0.f;
        #pragma unroll
        for (int i = 0; i < OUTC; i++) s += p[i];
        if (t < 8)
            g_pas2[nb + node] = make_float4(s, __expf(s), __expf(0.2f * s), 0.f);
        else
            g_ad2[nb + node] = s;
    }
}

// ---- layer-2 aggregation: warp/node, float2 lanes (l<20), NO MUFU in loop ----
__global__ void __launch_bounds__(256, 5) k_agg2(const float* __restrict__ b2,
                                                 float* __restrict__ out) {
    const int n = blockIdx.x * 8 + (threadIdx.x >> 5);
    const int l = threadIdx.x & 31;
    const int start = g_rowptr[n], end = g_rowptr[n + 1];
    const float ad = __ldg(&g_ad2[n]);
    const float E1d = __expf(ad);
    const float E5d = __expf(0.2f * ad);
    const float2* __restrict__ H = (const float2*)g_h2;
    const bool act = (l < 20);
    const float2 zz = make_float2(0.f, 0.f);

    float accx = 0.f, accy = 0.f, den = 0.f;
    for (int eb = start; eb < end; eb += 32) {
        int m = end - eb; if (m > 32) m = 32;
        int s = 0; float ex = 0.f;
        if (l < m) {
            s = __ldg(&g_csr_src[eb + l]);
            float4 P = __ldg(&g_pas2[s]);
            float v = P.x + ad;
            ex = (v > 0.f) ? P.y * E1d : P.z * E5d;
        }
        den += ex;
        #pragma unroll
        for (int j = 0; j < 32; j += 4) {
            if (j >= m) break;
            int   s0 = __shfl_sync(FULL, s,  j + 0);
            int   s1 = __shfl_sync(FULL, s,  j + 1);
            int   s2 = __shfl_sync(FULL, s,  j + 2);
            int   s3 = __shfl_sync(FULL, s,  j + 3);
            float x0 = __shfl_sync(FULL, ex, j + 0);
            float x1 = __shfl_sync(FULL, ex, j + 1);
            float x2 = __shfl_sync(FULL, ex, j + 2);
            float x3 = __shfl_sync(FULL, ex, j + 3);
            float2 r0 = act ? __ldg(&H[s0 * 20 + l]) : zz;
            float2 r1 = act ? __ldg(&H[s1 * 20 + l]) : zz;
            float2 r2 = act ? __ldg(&H[s2 * 20 + l]) : zz;
            float2 r3 = act ? __ldg(&H[s3 * 20 + l]) : zz;
            accx += x0 * r0.x + x1 * r1.x + x2 * r2.x + x3 * r3.x;
            accy += x0 * r0.y + x1 * r1.y + x2 * r2.y + x3 * r3.y;
        }
    }
    #pragma unroll
    for (int off = 1; off < 32; off <<= 1) den += __shfl_xor_sync(FULL, den, off);

    if (act) {
        float2 bb = __ldg(&((const float2*)b2)[l]);
        float2 r;
        r.x = accx / den + bb.x;
        r.y = accy / den + bb.y;
        ((float2*)out)[n * 20 + l] = r;
    }
}

extern "C" void kernel_launch(void* const* d_in, const int* in_sizes, int n_in,
                              void* d_out, int out_size) {
    const float* x   = (const float*)d_in[0];
    const int*   ei  = (const int*)  d_in[1];
    const float* W1  = (const float*)d_in[2];
    const float* as1 = (const float*)d_in[3];
    const float* ad1 = (const float*)d_in[4];
    const float* b1  = (const float*)d_in[5];
    const float* W2  = (const float*)d_in[6];
    const float* as2 = (const float*)d_in[7];
    const float* ad2 = (const float*)d_in[8];
    const float* b2  = (const float*)d_in[9];
    float* out = (float*)d_out;

    int nE = in_sizes[1] / 2;
    const int* src = ei;
    const int* dst = ei + nE;

    const int T = 256;
    int eg = (nE + T - 1) / T;

    static cudaStream_t s2 = nullptr;
    static cudaEvent_t evFork = nullptr, evJoin = nullptr;
    if (s2 == nullptr) {
        cudaStreamCreateWithFlags(&s2, cudaStreamNonBlocking);
        cudaEventCreateWithFlags(&evFork, cudaEventDisableTiming);
        cudaEventCreateWithFlags(&evJoin, cudaEventDisableTiming);
    }

    cudaEventRecord(evFork, 0);
    cudaStreamWaitEvent(s2, evFork, 0);
    k_gemm1<<<NN / 16, 256, 0, s2>>>(x, W1, as1, ad1);
    cudaEventRecord(evJoin, s2);

    k_init <<<(NN + T - 1) / T, T>>>();
    k_hist <<<eg, T>>>(dst, nE);
    k_scanA<<<SCANB, 1024>>>();
    k_scanB<<<1, 128>>>();
    k_scanC<<<SCANB, 1024>>>();
    k_fill <<<eg, T>>>(src, dst, nE);

    cudaStreamWaitEvent(0, evJoin, 0);

    k_agg1 <<<NN / 8, 256>>>(b1);
    k_gemm2<<<NN / 8, 320>>>(W2, as2, ad2);
    k_agg2 <<<NN / 8, 256>>>(b2, out);
}

// round 11
// speedup vs baseline: 1.0793x; 1.0793x over previous
#include <cuda_runtime.h>

#define NN    100000
#define EMAX  1700000
#define INC   128
#define H1DIM 64
#define HEADS 8
#define HID   8
#define OUTC  40
#define FULL  0xffffffffu
#define SCANB 98            // ceil(NN/1024)

// ---- scratch ----
__device__ float g_h1[NN * H1DIM];
__device__ float g_as1[NN * HEADS];
__device__ float g_ad1[NN * HEADS];
__device__ float g_h2[NN * OUTC];
__device__ float g_as2[NN];
__device__ float g_ad2[NN];
__device__ int   g_cnt[NN];
__device__ int   g_cur[NN];
__device__ int   g_rowptr[NN + 1];
__device__ int   g_blocksum[SCANB];
__device__ int   g_blockoff[SCANB];
__device__ int   g_csr_src[EMAX];

// ---- histogram of destinations (g_cnt/g_cur zeroed by memset nodes) ----
__global__ void __launch_bounds__(256) k_hist(const int* __restrict__ dst, int nE) {
    int e = blockIdx.x * blockDim.x + threadIdx.x;
    if (e < nE) atomicAdd(&g_cnt[dst[e]], 1);
}

// ---- scan phase A ----
__global__ void __launch_bounds__(1024) k_scanA() {
    __shared__ int sm[1024];
    int t = threadIdx.x;
    int i = blockIdx.x * 1024 + t;
    sm[t] = (i < NN) ? g_cnt[i] : 0;
    __syncthreads();
    for (int d = 512; d > 0; d >>= 1) {
        if (t < d) sm[t] += sm[t + d];
        __syncthreads();
    }
    if (t == 0) g_blocksum[blockIdx.x] = sm[0];
}

// ---- scan phase B ----
__global__ void __launch_bounds__(128) k_scanB() {
    __shared__ int sm[128];
    int t = threadIdx.x;
    int v = (t < SCANB) ? g_blocksum[t] : 0;
    sm[t] = v;
    __syncthreads();
    for (int d = 1; d < 128; d <<= 1) {
        int u = (t >= d) ? sm[t - d] : 0;
        __syncthreads();
        sm[t] += u;
        __syncthreads();
    }
    if (t < SCANB) g_blockoff[t] = sm[t] - v;
    if (t == SCANB - 1) g_rowptr[NN] = sm[t];
}

// ---- scan phase C ----
__global__ void __launch_bounds__(1024) k_scanC() {
    __shared__ int sm[1024];
    int t = threadIdx.x;
    int i = blockIdx.x * 1024 + t;
    int v = (i < NN) ? g_cnt[i] : 0;
    sm[t] = v;
    __syncthreads();
    for (int d = 1; d < 1024; d <<= 1) {
        int u = (t >= d) ? sm[t - d] : 0;
        __syncthreads();
        sm[t] += u;
        __syncthreads();
    }
    if (i < NN) g_rowptr[i] = g_blockoff[blockIdx.x] + sm[t] - v;
}

// ---- CSR fill ----
__global__ void __launch_bounds__(256) k_fill(const int* __restrict__ src,
                                              const int* __restrict__ dst, int nE) {
    int e = blockIdx.x * blockDim.x + threadIdx.x;
    if (e >= nE) return;
    int d = dst[e];
    int p = g_rowptr[d] + atomicAdd(&g_cur[d], 1);
    g_csr_src[p] = src[e];
}

// ---- layer-1 GEMM + attention dots ----
__global__ void __launch_bounds__(256) k_gemm1(
        const float* __restrict__ x,  const float* __restrict__ W1,
        const float* __restrict__ as_w, const float* __restrict__ ad_w) {
    __shared__ float wT[INC * H1DIM];
    __shared__ float xs[16 * INC];
    const int t = threadIdx.x;
    const int nb = blockIdx.x * 16;

    for (int i = t; i < H1DIM * INC; i += 256) {
        int f = i >> 7, k = i & 127;
        wT[k * H1DIM + f] = W1[i];
    }
    for (int i = t; i < 16 * INC; i += 256) {
        int node = nb + (i >> 7);
        xs[i] = x[node * INC + (i & 127)];
    }
    __syncthreads();

    const int f = t & 63;
    const int g = t >> 6;
    float acc[4] = {0.f, 0.f, 0.f, 0.f};

    const float4* xr0 = (const float4*)(xs + (g +  0) * INC);
    const float4* xr1 = (const float4*)(xs + (g +  4) * INC);
    const float4* xr2 = (const float4*)(xs + (g +  8) * INC);
    const float4* xr3 = (const float4*)(xs + (g + 12) * INC);

    #pragma unroll 4
    for (int k4 = 0; k4 < INC / 4; k4++) {
        int kb = k4 * 4;
        float w0 = wT[(kb + 0) * H1DIM + f];
        float w1 = wT[(kb + 1) * H1DIM + f];
        float w2 = wT[(kb + 2) * H1DIM + f];
        float w3 = wT[(kb + 3) * H1DIM + f];
        float4 v;
        v = xr0[k4]; acc[0] += v.x*w0 + v.y*w1 + v.z*w2 + v.w*w3;
        v = xr1[k4]; acc[1] += v.x*w0 + v.y*w1 + v.z*w2 + v.w*w3;
        v = xr2[k4]; acc[2] += v.x*w0 + v.y*w1 + v.z*w2 + v.w*w3;
        v = xr3[k4]; acc[3] += v.x*w0 + v.y*w1 + v.z*w2 + v.w*w3;
    }

    float aw = as_w[f], dw = ad_w[f];
    #pragma unroll
    for (int i = 0; i < 4; i++) {
        int node = nb + g + 4 * i;
        float vs = acc[i] * aw, vd = acc[i] * dw;
        #pragma unroll
        for (int off = 1; off < HID; off <<= 1) {
            vs += __shfl_xor_sync(FULL, vs, off);
            vd += __shfl_xor_sync(FULL, vd, off);
        }
        g_h1[node * H1DIM + f] = acc[i];
        if ((f & 7) == 0) {
            g_as1[node * HEADS + (f >> 3)] = vs;
            g_ad1[node * HEADS + (f >> 3)] = vd;
        }
    }
}

// ---- FUSED layer-1 aggregation + layer-2 GEMM + att2 dots ----
// 320 threads: warps 0-7 aggregate nodes nb..nb+7 (R6 agg1 body -> smem act),
// warps 8-9 stage W2^T into smem meanwhile. Then block-wide gemm2 from smem.
__global__ void __launch_bounds__(320) k_agg1g2(const float* __restrict__ b1,
                                                const float* __restrict__ W2,
                                                const float* __restrict__ as_w,
                                                const float* __restrict__ ad_w) {
    __shared__ float wT[H1DIM * OUTC];            // 10KB: wT[k*40+f] = W2[f*64+k]
    __shared__ __align__(16) float sact[8][H1DIM]; // 2KB: ELU'd layer-1 output
    __shared__ float ps[8 * OUTC];
    __shared__ float pd[8 * OUTC];
    const int t   = threadIdx.x;
    const int wid = t >> 5;
    const int l   = t & 31;
    const int nb  = blockIdx.x * 8;

    if (wid >= 8) {
        // stage W2 transposed while agg warps work
        for (int i = t - 256; i < OUTC * H1DIM; i += 64) {
            int f = i >> 6, k = i & 63;
            wT[k * OUTC + f] = W2[i];
        }
    } else {
        // ---- R6 agg1 body: warp per node, float2 lanes, prefetched ----
        const int n = nb + wid;
        const int start = g_rowptr[n], end = g_rowptr[n + 1];

        const int g  = l >> 3;    // edge slot for exp phase
        const int h  = l & 7;     // head for exp phase
        const int hl = l >> 2;    // head of this lane's channel pair
        const float adh = g_ad1[n * HEADS + h];
        const float2* __restrict__ H = (const float2*)g_h1;

        int m = end - start; if (m > 4) m = 4;
        int s = 0; float v = 0.f;
        if (g < m) {
            s = g_csr_src[start + g];
            v = g_as1[s * HEADS + h] + adh;
        }

        float accx = 0.f, accy = 0.f, den = 0.f;
        for (int eb = start; eb < end; eb += 4) {
            int ebn = eb + 4;
            int mn = end - ebn; if (mn > 4) mn = 4;
            int sn = 0; float vn = 0.f;
            if (g < mn) {
                sn = g_csr_src[ebn + g];
                vn = g_as1[sn * HEADS + h] + adh;
            }

            float lv = (v > 0.f) ? v : 0.2f * v;
            float ex = (g < m) ? __expf(lv) : 0.f;
            den += ex;

            int s0 = __shfl_sync(FULL, s, 0);
            int s1 = __shfl_sync(FULL, s, 8);
            int s2 = __shfl_sync(FULL, s, 16);
            int s3 = __shfl_sync(FULL, s, 24);
            float x0 = __shfl_sync(FULL, ex, hl);
            float x1 = __shfl_sync(FULL, ex, 8 + hl);
            float x2 = __shfl_sync(FULL, ex, 16 + hl);
            float x3 = __shfl_sync(FULL, ex, 24 + hl);

            float2 r0 = H[s0 * 32 + l];
            float2 r1 = H[s1 * 32 + l];
            float2 r2 = H[s2 * 32 + l];
            float2 r3 = H[s3 * 32 + l];

            accx += x0*r0.x + x1*r1.x + x2*r2.x + x3*r3.x;
            accy += x0*r0.y + x1*r1.y + x2*r2.y + x3*r3.y;

            m = mn; s = sn; v = vn;
        }
        den += __shfl_xor_sync(FULL, den, 8);
        den += __shfl_xor_sync(FULL, den, 16);   // lane l: denom of head l&7
        float dd = __shfl_sync(FULL, den, hl);

        float2 bb = ((const float2*)b1)[l];
        float o0 = accx / dd + bb.x;
        float o1 = accy / dd + bb.y;
        float2 r;
        r.x = (o0 > 0.f) ? o0 : expm1f(o0);
        r.y = (o1 > 0.f) ? o1 : expm1f(o1);
        ((float2*)sact[wid])[l] = r;             // stays in smem — no global trip
    }
    __syncthreads();

    // ---- gemm2 phase (R6 body, act from smem) ----
    const int f = t % OUTC;
    const int local = t / OUTC;
    const float4* ar = (const float4*)(sact[local]);
    float acc = 0.f;
    #pragma unroll 4
    for (int k4 = 0; k4 < H1DIM / 4; k4++) {
        int kb = k4 * 4;
        float4 vv = ar[k4];
        acc += vv.x * wT[(kb + 0) * OUTC + f];
        acc += vv.y * wT[(kb + 1) * OUTC + f];
        acc += vv.z * wT[(kb + 2) * OUTC + f];
        acc += vv.w * wT[(kb + 3) * OUTC + f];
    }
    g_h2[(nb + local) * OUTC + f] = acc;
    ps[local * OUTC + f] = acc * as_w[f];
    pd[local * OUTC + f] = acc * ad_w[f];
    __syncthreads();

    if (t < 16) {
        int node = t & 7;
        const float* p = (t < 8) ? (ps + node * OUTC) : (pd + node * OUTC);
        float ss = 0.f;
        #pragma unroll
        for (int i = 0; i < OUTC; i++) ss += p[i];
        if (t < 8) g_as2[nb + node] = ss;
        else       g_ad2[nb + node] = ss;
    }
}

// ---- layer-2 aggregation: warp/node, float2 lanes (l<20), 4-way unroll ----
__global__ void __launch_bounds__(256, 5) k_agg2(const float* __restrict__ b2,
                                                 float* __restrict__ out) {
    const int n = blockIdx.x * 8 + (threadIdx.x >> 5);
    const int l = threadIdx.x & 31;
    const int start = g_rowptr[n], end = g_rowptr[n + 1];
    const float ad = __ldg(&g_ad2[n]);
    const float2* __restrict__ H = (const float2*)g_h2;
    const bool act = (l < 20);
    const float2 zz = make_float2(0.f, 0.f);

    float accx = 0.f, accy = 0.f, den = 0.f;
    for (int eb = start; eb < end; eb += 32) {
        int m = end - eb; if (m > 32) m = 32;
        int s = 0; float ex = 0.f;
        if (l < m) {
            s = __ldg(&g_csr_src[eb + l]);
            float v = __ldg(&g_as2[s]) + ad;
            v = (v > 0.f) ? v : 0.2f * v;
            ex = __expf(v);
        }
        den += ex;
        #pragma unroll
        for (int j = 0; j < 32; j += 4) {
            if (j >= m) break;
            int   s0 = __shfl_sync(FULL, s,  j + 0);
            int   s1 = __shfl_sync(FULL, s,  j + 1);
            int   s2 = __shfl_sync(FULL, s,  j + 2);
            int   s3 = __shfl_sync(FULL, s,  j + 3);
            float x0 = __shfl_sync(FULL, ex, j + 0);
            float x1 = __shfl_sync(FULL, ex, j + 1);
            float x2 = __shfl_sync(FULL, ex, j + 2);
            float x3 = __shfl_sync(FULL, ex, j + 3);
            float2 r0 = act ? __ldg(&H[s0 * 20 + l]) : zz;
            float2 r1 = act ? __ldg(&H[s1 * 20 + l]) : zz;
            float2 r2 = act ? __ldg(&H[s2 * 20 + l]) : zz;
            float2 r3 = act ? __ldg(&H[s3 * 20 + l]) : zz;
            accx += x0 * r0.x + x1 * r1.x + x2 * r2.x + x3 * r3.x;
            accy += x0 * r0.y + x1 * r1.y + x2 * r2.y + x3 * r3.y;
        }
    }
    #pragma unroll
    for (int off = 1; off < 32; off <<= 1) den += __shfl_xor_sync(FULL, den, off);

    if (act) {
        float2 bb = __ldg(&((const float2*)b2)[l]);
        float2 r;
        r.x = accx / den + bb.x;
        r.y = accy / den + bb.y;
        ((float2*)out)[n * 20 + l] = r;
    }
}

extern "C" void kernel_launch(void* const* d_in, const int* in_sizes, int n_in,
                              void* d_out, int out_size) {
    const float* x   = (const float*)d_in[0];
    const int*   ei  = (const int*)  d_in[1];
    const float* W1  = (const float*)d_in[2];
    const float* as1 = (const float*)d_in[3];
    const float* ad1 = (const float*)d_in[4];
    const float* b1  = (const float*)d_in[5];
    const float* W2  = (const float*)d_in[6];
    const float* as2 = (const float*)d_in[7];
    const float* ad2 = (const float*)d_in[8];
    const float* b2  = (const float*)d_in[9];
    float* out = (float*)d_out;

    int nE = in_sizes[1] / 2;
    const int* src = ei;
    const int* dst = ei + nE;

    const int T = 256;
    int eg = (nE + T - 1) / T;

    static cudaStream_t s2 = nullptr;
    static cudaEvent_t evFork = nullptr, evJoin = nullptr;
    static int* cnt_addr = nullptr;
    static int* cur_addr = nullptr;
    if (s2 == nullptr) {
        cudaStreamCreateWithFlags(&s2, cudaStreamNonBlocking);
        cudaEventCreateWithFlags(&evFork, cudaEventDisableTiming);
        cudaEventCreateWithFlags(&evJoin, cudaEventDisableTiming);
        cudaGetSymbolAddress((void**)&cnt_addr, g_cnt);
        cudaGetSymbolAddress((void**)&cur_addr, g_cur);
    }

    // fork: gemm1 runs concurrently with CSR build
    cudaEventRecord(evFork, 0);
    cudaStreamWaitEvent(s2, evFork, 0);
    k_gemm1<<<NN / 16, 256, 0, s2>>>(x, W1, as1, ad1);
    cudaEventRecord(evJoin, s2);

    // main stream: CSR build
    cudaMemsetAsync(cnt_addr, 0, NN * sizeof(int), 0);
    cudaMemsetAsync(cur_addr, 0, NN * sizeof(int), 0);
    k_hist <<<eg, T>>>(dst, nE);
    k_scanA<<<SCANB, 1024>>>();
    k_scanB<<<1, 128>>>();
    k_scanC<<<SCANB, 1024>>>();
    k_fill <<<eg, T>>>(src, dst, nE);

    cudaStreamWaitEvent(0, evJoin, 0);

    k_agg1g2<<<NN / 8, 320>>>(b1, W2, as2, ad2);
    k_agg2  <<<NN / 8, 256>>>(b2, out);
}